// round 6
// baseline (speedup 1.0000x reference)
#include <cuda_runtime.h>

// Local contrast normalization, fused. Dataflow:
//  S01: LDG x (16x2 window per item, 2x redundant) -> scalar h-conv (imm FFMA) -> stT smem
//  S2 : v-conv (packed f32x2 over col-pairs) -> mean; d = (x(LDG)-mean)*mask -> sd smem
//  S3 : scalar h-conv of d^2 (imm FFMA) -> st2 smem (col-pair packed per y)
//  S4 : v-conv (packed) -> var; out = (var>0.25) ? d*rsqrt(var) : d
// Both convs SAME zero-pad; taps u[i]=exp(-(i-4.5)^2/3)/S.

typedef unsigned long long u64;
typedef ulonglong2 u64x2;

static constexpr int HH = 512, WW = 512;
static constexpr int TY = 32, TX = 64;

static constexpr int STP = 50;  // stT: u64 [36 cp][48 y]   (400B row = 25*16, odd)
static constexpr int SDP = 76;  // sd:  float [40 r][72 c]  (304B row = 19*16, odd)
static constexpr int T2P = 42;  // st2: u64 [32 cp][40 y]   (336B row = 21*16, odd) aliases stT

#define K0f 0.000381553f
#define K1f 0.00549127f
#define K2f 0.04057532f
#define K3f 0.15392929f
#define K4f 0.29981330f

union F2 { u64 v; float f[2]; };

__device__ __forceinline__ u64 pk(float a, float b) {
    F2 t; t.f[0] = a; t.f[1] = b; return t.v;
}
__device__ __forceinline__ u64 f2mul(u64 a, u64 b) {
    u64 d; asm("mul.rn.f32x2 %0, %1, %2;" : "=l"(d) : "l"(a), "l"(b)); return d;
}
__device__ __forceinline__ u64 f2fma(u64 a, u64 b, u64 c) {
    u64 d; asm("fma.rn.f32x2 %0, %1, %2, %3;" : "=l"(d) : "l"(a), "l"(b), "l"(c)); return d;
}

// scalar 9-tap conv, literal taps -> FFMA-imm
__device__ __forceinline__ float conv9s(const float* a) {
    float acc = K0f * a[0];
    acc = fmaf(K1f, a[1], acc);
    acc = fmaf(K2f, a[2], acc);
    acc = fmaf(K3f, a[3], acc);
    acc = fmaf(K4f, a[4], acc);
    acc = fmaf(K4f, a[5], acc);
    acc = fmaf(K3f, a[6], acc);
    acc = fmaf(K2f, a[7], acc);
    acc = fmaf(K1f, a[8], acc);
    return acc;
}
// packed 9-tap conv
__device__ __forceinline__ u64 conv9p(const u64* a, const u64 kv[5]) {
    u64 acc = f2mul(kv[0], a[0]);
    acc = f2fma(kv[1], a[1], acc);
    acc = f2fma(kv[2], a[2], acc);
    acc = f2fma(kv[3], a[3], acc);
    acc = f2fma(kv[4], a[4], acc);
    acc = f2fma(kv[4], a[5], acc);
    acc = f2fma(kv[3], a[6], acc);
    acc = f2fma(kv[2], a[7], acc);
    acc = f2fma(kv[1], a[8], acc);
    return acc;
}

__global__ __launch_bounds__(256)
void lcn_kernel(const float* __restrict__ x, float* __restrict__ out) {
    __shared__ __align__(16) u64 sb[36 * STP];     // stT, later st2
    __shared__ __align__(16) float sd[40 * SDP];   // demeaned, row-major

    const int tid = threadIdx.x;
    const int ox = blockIdx.x * TX;
    const int oy = blockIdx.y * TY;
    const long base = (long)blockIdx.z * (HH * WW);

    u64 kv[5];
    kv[0] = pk(K0f, K0f); kv[1] = pk(K1f, K1f); kv[2] = pk(K2f, K2f);
    kv[3] = pk(K3f, K3f); kv[4] = pk(K4f, K4f);
    const u64 neg1 = pk(-1.f, -1.f);
    const bool interior = (ox != 0) && (ox != WW - TX) && (oy != 0) && (oy != HH - TY);

    // ---------- S01: global load + scalar h-conv -> stT[cp][y] ----------
    // item (r, s): t-cols 8s..8s+7 at t-rows (2r, 2r+1); x window gx0..gx0+15.
    if (tid < 216) {
        int r = tid % 24, s = tid / 24;
        const int gye = oy - 8 + 2 * r;
        const int gx0 = ox - 8 + 8 * s;
        const float* pe = x + base + (long)gye * WW + gx0;

        // even row
        float xw[16];
        if (interior) {
            #pragma unroll
            for (int q = 0; q < 4; q++) {
                float4 v = *(const float4*)(pe + 4 * q);
                xw[4*q] = v.x; xw[4*q+1] = v.y; xw[4*q+2] = v.z; xw[4*q+3] = v.w;
            }
        } else {
            bool rok = (unsigned)gye < (unsigned)HH;
            #pragma unroll
            for (int q = 0; q < 4; q++) {
                float4 v = make_float4(0.f, 0.f, 0.f, 0.f);
                if (rok && (unsigned)(gx0 + 4*q) < (unsigned)WW)
                    v = *(const float4*)(pe + 4 * q);
                xw[4*q] = v.x; xw[4*q+1] = v.y; xw[4*q+2] = v.z; xw[4*q+3] = v.w;
            }
        }
        float te[8];
        #pragma unroll
        for (int k = 0; k < 8; k++) te[k] = conv9s(xw + k);
        #pragma unroll
        for (int m = 0; m < 4; m++)
            *(u64*)(sb + (4*s + m) * STP + 2*r) = pk(te[2*m], te[2*m+1]);

        // odd row
        const float* po = pe + WW;
        if (interior) {
            #pragma unroll
            for (int q = 0; q < 4; q++) {
                float4 v = *(const float4*)(po + 4 * q);
                xw[4*q] = v.x; xw[4*q+1] = v.y; xw[4*q+2] = v.z; xw[4*q+3] = v.w;
            }
        } else {
            bool rok = (unsigned)(gye + 1) < (unsigned)HH;
            #pragma unroll
            for (int q = 0; q < 4; q++) {
                float4 v = make_float4(0.f, 0.f, 0.f, 0.f);
                if (rok && (unsigned)(gx0 + 4*q) < (unsigned)WW)
                    v = *(const float4*)(po + 4 * q);
                xw[4*q] = v.x; xw[4*q+1] = v.y; xw[4*q+2] = v.z; xw[4*q+3] = v.w;
            }
        }
        float to_[8];
        #pragma unroll
        for (int k = 0; k < 8; k++) to_[k] = conv9s(xw + k);
        #pragma unroll
        for (int m = 0; m < 4; m++)
            *(u64*)(sb + (4*s + m) * STP + 2*r + 1) = pk(to_[2*m], to_[2*m+1]);
    }
    __syncthreads();

    // ---------- S2: packed v-conv -> mean; d = (x - mean)*mask -> sd ----------
    // item (cp, rb): cols (2cp, 2cp+1) [gx = ox-4+2cp], d rows y0..y0+7.
    if (tid < 180) {
        int cp = tid % 36, rb = tid / 36;
        const int y0 = 8 * rb;
        const u64* wb = sb + cp * STP + y0;
        const int gx0 = ox - 4 + 2 * cp;
        const float* xp = x + base + (long)(oy - 4 + y0) * WW + gx0;
        float* sdb = sd + y0 * SDP + 2 * cp;

        u64 a[16];
        #pragma unroll
        for (int q = 0; q < 6; q++) { u64x2 v = ((const u64x2*)wb)[q]; a[2*q] = v.x; a[2*q+1] = v.y; }

        if (interior) {
            #pragma unroll
            for (int k = 0; k < 4; k++) {
                u64 mp = conv9p(a + k, kv);
                u64 xv = *(const u64*)(xp + (long)k * WW);
                *(u64*)(sdb + k * SDP) = f2fma(mp, neg1, xv);
            }
            #pragma unroll
            for (int q = 6; q < 8; q++) { u64x2 v = ((const u64x2*)wb)[q]; a[2*q] = v.x; a[2*q+1] = v.y; }
            #pragma unroll
            for (int k = 4; k < 8; k++) {
                u64 mp = conv9p(a + k, kv);
                u64 xv = *(const u64*)(xp + (long)k * WW);
                *(u64*)(sdb + k * SDP) = f2fma(mp, neg1, xv);
            }
        } else {
            const bool cE = (unsigned)gx0 < (unsigned)WW;
            const bool cO = (unsigned)(gx0 + 1) < (unsigned)WW;
            #pragma unroll
            for (int q = 6; q < 8; q++) { u64x2 v = ((const u64x2*)wb)[q]; a[2*q] = v.x; a[2*q+1] = v.y; }
            #pragma unroll
            for (int k = 0; k < 8; k++) {
                u64 mp = conv9p(a + k, kv);
                int gy = oy - 4 + y0 + k;
                bool rok = (unsigned)gy < (unsigned)HH;
                float e = (rok && cE) ? xp[(long)k * WW] : 0.f;
                float o = (rok && cO) ? xp[(long)k * WW + 1] : 0.f;
                u64 msk = pk((rok && cE) ? 1.f : 0.f, (rok && cO) ? 1.f : 0.f);
                u64 d = f2mul(f2fma(mp, neg1, pk(e, o)), msk);
                *(u64*)(sdb + k * SDP) = d;
            }
        }
    }
    __syncthreads();

    // ---------- S3: scalar h-conv of d^2 -> st2[cp][y] (aliases sb) ----------
    // item (rr, s): t2 cols 16s..16s+15 at row rr; d window cols 16s..16s+23.
    if (tid < 160) {
        int rr = tid % 40, s = tid / 40;
        const int c0 = 16 * s;
        const float* dp = sd + rr * SDP + c0;
        float q[24];
        #pragma unroll
        for (int i = 0; i < 6; i++) {
            float4 v = ((const float4*)dp)[i];
            q[4*i]   = v.x * v.x;
            q[4*i+1] = v.y * v.y;
            q[4*i+2] = v.z * v.z;
            q[4*i+3] = v.w * v.w;
        }
        float t[16];
        #pragma unroll
        for (int k = 0; k < 16; k++) t[k] = conv9s(q + k);
        #pragma unroll
        for (int m = 0; m < 8; m++)
            *(u64*)(sb + (8*s + m) * T2P + rr) = pk(t[2*m], t[2*m+1]);
    }
    __syncthreads();

    // ---------- S4: packed v-conv -> var; finalize; STG.64 ----------
    // item (cp, rb): out cols (ox+2cp, +1), out rows y0..y0+7.
    if (tid < 128) {
        int cp = tid & 31, rb = tid >> 5;
        const int y0 = 8 * rb;
        const u64* wb = sb + cp * T2P + y0;
        u64 a[16];
        #pragma unroll
        for (int q = 0; q < 6; q++) { u64x2 v = ((const u64x2*)wb)[q]; a[2*q] = v.x; a[2*q+1] = v.y; }
        const float* sdb = sd + (y0 + 4) * SDP + 2 * cp + 4;
        float* ob = out + base + (long)(oy + y0) * WW + (ox + 2 * cp);
        #pragma unroll
        for (int k = 0; k < 4; k++) {
            u64 vp = conv9p(a + k, kv);
            F2 V, D; V.v = vp; D.v = *(const u64*)(sdb + k * SDP);
            float m0 = (V.f[0] > 0.25f) ? rsqrtf(V.f[0]) : 1.f;
            float m1 = (V.f[1] > 0.25f) ? rsqrtf(V.f[1]) : 1.f;
            *(float2*)(ob + (long)k * WW) = make_float2(D.f[0] * m0, D.f[1] * m1);
        }
        #pragma unroll
        for (int q = 6; q < 8; q++) { u64x2 v = ((const u64x2*)wb)[q]; a[2*q] = v.x; a[2*q+1] = v.y; }
        #pragma unroll
        for (int k = 4; k < 8; k++) {
            u64 vp = conv9p(a + k, kv);
            F2 V, D; V.v = vp; D.v = *(const u64*)(sdb + k * SDP);
            float m0 = (V.f[0] > 0.25f) ? rsqrtf(V.f[0]) : 1.f;
            float m1 = (V.f[1] > 0.25f) ? rsqrtf(V.f[1]) : 1.f;
            *(float2*)(ob + (long)k * WW) = make_float2(D.f[0] * m0, D.f[1] * m1);
        }
    }
}

extern "C" void kernel_launch(void* const* d_in, const int* in_sizes, int n_in,
                              void* d_out, int out_size) {
    const float* x = (const float*)d_in[0];
    float* out = (float*)d_out;
    int B = in_sizes[0] / (HH * WW);
    dim3 grid(WW / TX, HH / TY, B);
    lcn_kernel<<<grid, 256>>>(x, out);
}

// round 7
// speedup vs baseline: 1.1628x; 1.1628x over previous
#include <cuda_runtime.h>

// Local contrast normalization, fused, all-row-major no-transpose design.
//  S0: coalesced LDG x tile -> smem (row-major)
//  S1: scalar h-conv (FFMA-imm), float4 in/out -> stT (row-major)
//  S2: v-conv as col-quad f32x2 over stT rows; d = (x(LDG coalesced) - mean) masked -> sd
//  S3: scalar h-conv of d^2 -> st2 (row-major)
//  S4: v-conv col-quad -> var; out = d * (var>0.25 ? rsqrt(var) : 1), STG.128
// Taps u[i] = exp(-(i-4.5)^2/3)/S (asymmetric center), SAME zero-pad.

typedef unsigned long long u64;

static constexpr int HH = 512, WW = 512;
static constexpr int TX = 128, TY = 32;

// pitches in floats; pitch*4 bytes = odd multiple of 16 -> conflict-free phases
static constexpr int PX = 148;   // sx : 48 rows x 144 used  (592B = 37*16)
static constexpr int PT = 140;   // stT: 48 rows x 136 used  (560B = 35*16)
static constexpr int PD = 140;   // sd : 40 rows x 136 used  (aliases sx region)
static constexpr int P2 = 132;   // st2: 40 rows x 128 used  (528B = 33*16, aliases stT)

static constexpr int OFF_X = 48 * PT;                       // float offset of sx/sd region
static constexpr int SMEM_BYTES = (OFF_X + 48 * PX) * 4;    // 55296

#define K0f 0.000381553f
#define K1f 0.00549127f
#define K2f 0.04057532f
#define K3f 0.15392929f
#define K4f 0.29981330f

union V4 { float4 f; u64 u[2]; };
union V2 { u64 u; float s[2]; };

__device__ __forceinline__ u64 pk2(float a, float b) {
    V2 t; t.s[0] = a; t.s[1] = b; return t.u;
}
__device__ __forceinline__ u64 f2mul(u64 a, u64 b) {
    u64 d; asm("mul.rn.f32x2 %0, %1, %2;" : "=l"(d) : "l"(a), "l"(b)); return d;
}
__device__ __forceinline__ u64 f2fma(u64 a, u64 b, u64 c) {
    u64 d; asm("fma.rn.f32x2 %0, %1, %2, %3;" : "=l"(d) : "l"(a), "l"(b), "l"(c)); return d;
}

// scalar 9-tap conv, literal taps -> FFMA-imm (rt 1)
__device__ __forceinline__ float conv9s(const float* a) {
    float acc = K0f * a[0];
    acc = fmaf(K1f, a[1], acc);
    acc = fmaf(K2f, a[2], acc);
    acc = fmaf(K3f, a[3], acc);
    acc = fmaf(K4f, a[4], acc);
    acc = fmaf(K4f, a[5], acc);
    acc = fmaf(K3f, a[6], acc);
    acc = fmaf(K2f, a[7], acc);
    acc = fmaf(K1f, a[8], acc);
    return acc;
}
// packed 9-tap conv
__device__ __forceinline__ u64 conv9p(const u64* a, const u64 kv[5]) {
    u64 acc = f2mul(kv[0], a[0]);
    acc = f2fma(kv[1], a[1], acc);
    acc = f2fma(kv[2], a[2], acc);
    acc = f2fma(kv[3], a[3], acc);
    acc = f2fma(kv[4], a[4], acc);
    acc = f2fma(kv[4], a[5], acc);
    acc = f2fma(kv[3], a[6], acc);
    acc = f2fma(kv[2], a[7], acc);
    acc = f2fma(kv[1], a[8], acc);
    return acc;
}

__global__ __launch_bounds__(256)
void lcn_kernel(const float* __restrict__ x, float* __restrict__ out) {
    extern __shared__ float sm[];
    float* smT = sm;            // stT, later st2
    float* smX = sm + OFF_X;    // sx, later sd

    const int tid = threadIdx.x;
    const int ox = blockIdx.x * TX;
    const int oy = blockIdx.y * TY;
    const long base = (long)blockIdx.z * (HH * WW);

    u64 kv[5];
    kv[0] = pk2(K0f, K0f); kv[1] = pk2(K1f, K1f); kv[2] = pk2(K2f, K2f);
    kv[3] = pk2(K3f, K3f); kv[4] = pk2(K4f, K4f);
    const u64 neg1 = pk2(-1.f, -1.f);

    // ---------- S0: coalesced load of x tile [48 x 144], row-major ----------
    #pragma unroll 1
    for (int i = tid; i < 48 * 36; i += 256) {
        int r = i / 36, c4 = i - 36 * r;
        int gy = oy - 8 + r, gx = ox - 8 + 4 * c4;   // gx multiple of 4
        float4 v = make_float4(0.f, 0.f, 0.f, 0.f);
        if ((unsigned)gy < (unsigned)HH && (unsigned)gx < (unsigned)WW)
            v = *(const float4*)(x + base + (long)gy * WW + gx);
        *(float4*)(smX + r * PX + 4 * c4) = v;
    }
    __syncthreads();

    // ---------- S1: scalar h-conv of x -> stT [48 x 136] ----------
    // item (r, s): t-cols 16s..16s+15 (seg 8: only 8 cols)
    #pragma unroll 1
    for (int i = tid; i < 432; i += 256) {
        int r = i % 48, s = i / 48;
        const float* sp = smX + r * PX + 16 * s;
        float* dp = smT + r * PT + 16 * s;
        float a[24];
        #pragma unroll
        for (int q = 0; q < 4; q++) {
            float4 v = ((const float4*)sp)[q];
            a[4*q] = v.x; a[4*q+1] = v.y; a[4*q+2] = v.z; a[4*q+3] = v.w;
        }
        float o[16];
        #pragma unroll
        for (int k = 0; k < 8; k++) o[k] = conv9s(a + k);
        if (s < 8) {
            #pragma unroll
            for (int q = 4; q < 6; q++) {
                float4 v = ((const float4*)sp)[q];
                a[4*q] = v.x; a[4*q+1] = v.y; a[4*q+2] = v.z; a[4*q+3] = v.w;
            }
            #pragma unroll
            for (int k = 8; k < 16; k++) o[k] = conv9s(a + k);
            #pragma unroll
            for (int q = 0; q < 4; q++)
                ((float4*)dp)[q] = make_float4(o[4*q], o[4*q+1], o[4*q+2], o[4*q+3]);
        } else {
            ((float4*)dp)[0] = make_float4(o[0], o[1], o[2], o[3]);
            ((float4*)dp)[1] = make_float4(o[4], o[5], o[6], o[7]);
        }
    }
    __syncthreads();

    // ---------- S2: v-conv (col-quads) -> mean; d = (x - mean)*mask -> sd ----------
    // item (cq, ck): cols 4cq..4cq+3 (img ox-4+4cq..), d rows 8ck..8ck+7
    if (tid < 170) {
        int cq = tid % 34, ck = tid / 34;
        const int y0 = 8 * ck;
        const float* tp = smT + y0 * PT + 4 * cq;
        const int gx0 = ox - 4 + 4 * cq;
        const float* xp = x + base + (long)(oy - 4 + y0) * WW + gx0;
        float* dp = smX + y0 * PD + 4 * cq;
        const bool colok = (unsigned)gx0 < (unsigned)WW;   // full quad in-image (gx0 mult of 4)

        u64 a0[16], a1[16];
        #pragma unroll
        for (int q = 0; q < 12; q++) {
            V4 v; v.f = *(const float4*)(tp + q * PT);
            a0[q] = v.u[0]; a1[q] = v.u[1];
        }
        #pragma unroll
        for (int k = 0; k < 8; k++) {
            if (k == 4) {
                #pragma unroll
                for (int q = 12; q < 16; q++) {
                    V4 v; v.f = *(const float4*)(tp + q * PT);
                    a0[q] = v.u[0]; a1[q] = v.u[1];
                }
            }
            u64 m0 = conv9p(a0 + k, kv);
            u64 m1 = conv9p(a1 + k, kv);
            int gy = oy - 4 + y0 + k;
            bool ok = colok && ((unsigned)gy < (unsigned)HH);
            V4 xv; xv.f = make_float4(0.f, 0.f, 0.f, 0.f);
            if (ok) xv.f = *(const float4*)(xp + (long)k * WW);
            V4 w;
            w.u[0] = ok ? f2fma(m0, neg1, xv.u[0]) : 0ULL;
            w.u[1] = ok ? f2fma(m1, neg1, xv.u[1]) : 0ULL;
            *(float4*)(dp + k * PD) = w.f;
        }
    }
    __syncthreads();

    // ---------- S3: scalar h-conv of d^2 -> st2 [40 x 128] ----------
    #pragma unroll 1
    for (int i = tid; i < 320; i += 256) {
        int y = i % 40, s = i / 40;
        const float* dpp = smX + y * PD + 16 * s;
        float a[24];
        #pragma unroll
        for (int q = 0; q < 6; q++) {
            float4 v = ((const float4*)dpp)[q];
            a[4*q]   = v.x * v.x;
            a[4*q+1] = v.y * v.y;
            a[4*q+2] = v.z * v.z;
            a[4*q+3] = v.w * v.w;
        }
        float* tp2 = smT + y * P2 + 16 * s;
        #pragma unroll
        for (int q = 0; q < 4; q++) {
            float4 o;
            o.x = conv9s(a + 4*q);
            o.y = conv9s(a + 4*q + 1);
            o.z = conv9s(a + 4*q + 2);
            o.w = conv9s(a + 4*q + 3);
            ((float4*)tp2)[q] = o;
        }
    }
    __syncthreads();

    // ---------- S4: v-conv (col-quads) -> var; finalize; STG.128 ----------
    if (tid < 128) {
        int cq = tid & 31, ck = tid >> 5;
        const int y0 = 8 * ck;
        const float* tp = smT + y0 * P2 + 4 * cq;
        const float* dpp = smX + (y0 + 4) * PD + 4 * cq + 4;
        float* op = out + base + (long)(oy + y0) * WW + ox + 4 * cq;

        u64 b0[16], b1[16];
        #pragma unroll
        for (int q = 0; q < 12; q++) {
            V4 v; v.f = *(const float4*)(tp + q * P2);
            b0[q] = v.u[0]; b1[q] = v.u[1];
        }
        #pragma unroll
        for (int k = 0; k < 8; k++) {
            if (k == 4) {
                #pragma unroll
                for (int q = 12; q < 16; q++) {
                    V4 v; v.f = *(const float4*)(tp + q * P2);
                    b0[q] = v.u[0]; b1[q] = v.u[1];
                }
            }
            V2 v0, v1;
            v0.u = conv9p(b0 + k, kv);
            v1.u = conv9p(b1 + k, kv);
            float4 dv = *(const float4*)(dpp + k * PD);
            float4 r;
            r.x = dv.x * ((v0.s[0] > 0.25f) ? rsqrtf(v0.s[0]) : 1.f);
            r.y = dv.y * ((v0.s[1] > 0.25f) ? rsqrtf(v0.s[1]) : 1.f);
            r.z = dv.z * ((v1.s[0] > 0.25f) ? rsqrtf(v1.s[0]) : 1.f);
            r.w = dv.w * ((v1.s[1] > 0.25f) ? rsqrtf(v1.s[1]) : 1.f);
            *(float4*)(op + (long)k * WW) = r;
        }
    }
}

extern "C" void kernel_launch(void* const* d_in, const int* in_sizes, int n_in,
                              void* d_out, int out_size) {
    const float* x = (const float*)d_in[0];
    float* out = (float*)d_out;
    int B = in_sizes[0] / (HH * WW);
    cudaFuncSetAttribute(lcn_kernel, cudaFuncAttributeMaxDynamicSharedMemorySize, SMEM_BYTES);
    dim3 grid(WW / TX, HH / TY, B);
    lcn_kernel<<<grid, 256, SMEM_BYTES>>>(x, out);
}

// round 8
// speedup vs baseline: 1.3787x; 1.1857x over previous
#include <cuda_runtime.h>

// Local contrast normalization, fused, all-row-major design, occupancy-tuned.
//  S0: coalesced LDG x tile -> smem (row-major)
//  S1: scalar h-conv (FFMA-imm), float4 in/out -> stT (row-major)
//  S2: v-conv as 2-col u64 f32x2 items; d = (x(LDG) - mean)*mask -> sd
//  S3: scalar h-conv of d^2 (FFMA-imm) -> st2 (row-major)
//  S4: v-conv 2-col u64 -> var; out = d * (var>0.25 ? rsqrt(var) : 1), STG.64
// Taps u[i] = exp(-(i-4.5)^2/3)/S (asymmetric center), SAME zero-pad.

typedef unsigned long long u64;

static constexpr int HH = 512, WW = 512;
static constexpr int TX = 128, TY = 32;

// pitches in floats; pitch*4 bytes = odd multiple of 16 -> conflict-free f4 phases
static constexpr int PX = 148;   // sx : 48 rows x 144 used  (592B = 37*16)
static constexpr int PT = 140;   // stT: 48 rows x 136 used  (560B = 35*16)
static constexpr int PD = 140;   // sd : 40 rows x 136 used  (aliases sx region)
static constexpr int P2 = 132;   // st2: 40 rows x 128 used  (528B = 33*16, aliases stT)

static constexpr int OFF_X = 48 * PT;                       // float offset of sx/sd region
static constexpr int SMEM_BYTES = (OFF_X + 48 * PX) * 4;    // 55296

#define K0f 0.000381553f
#define K1f 0.00549127f
#define K2f 0.04057532f
#define K3f 0.15392929f
#define K4f 0.29981330f

union V2 { u64 u; float s[2]; };

__device__ __forceinline__ u64 pk2(float a, float b) {
    V2 t; t.s[0] = a; t.s[1] = b; return t.u;
}
__device__ __forceinline__ u64 f2mul(u64 a, u64 b) {
    u64 d; asm("mul.rn.f32x2 %0, %1, %2;" : "=l"(d) : "l"(a), "l"(b)); return d;
}
__device__ __forceinline__ u64 f2fma(u64 a, u64 b, u64 c) {
    u64 d; asm("fma.rn.f32x2 %0, %1, %2, %3;" : "=l"(d) : "l"(a), "l"(b), "l"(c)); return d;
}

// scalar 9-tap conv, literal taps -> FFMA-imm (rt 1)
__device__ __forceinline__ float conv9s(const float* a) {
    float acc = K0f * a[0];
    acc = fmaf(K1f, a[1], acc);
    acc = fmaf(K2f, a[2], acc);
    acc = fmaf(K3f, a[3], acc);
    acc = fmaf(K4f, a[4], acc);
    acc = fmaf(K4f, a[5], acc);
    acc = fmaf(K3f, a[6], acc);
    acc = fmaf(K2f, a[7], acc);
    acc = fmaf(K1f, a[8], acc);
    return acc;
}
// packed 9-tap conv
__device__ __forceinline__ u64 conv9p(const u64* a, const u64 kv[5]) {
    u64 acc = f2mul(kv[0], a[0]);
    acc = f2fma(kv[1], a[1], acc);
    acc = f2fma(kv[2], a[2], acc);
    acc = f2fma(kv[3], a[3], acc);
    acc = f2fma(kv[4], a[4], acc);
    acc = f2fma(kv[4], a[5], acc);
    acc = f2fma(kv[3], a[6], acc);
    acc = f2fma(kv[2], a[7], acc);
    acc = f2fma(kv[1], a[8], acc);
    return acc;
}

__global__ __launch_bounds__(256, 4)
void lcn_kernel(const float* __restrict__ x, float* __restrict__ out) {
    extern __shared__ float sm[];
    float* smT = sm;            // stT, later st2
    float* smX = sm + OFF_X;    // sx, later sd

    const int tid = threadIdx.x;
    const int ox = blockIdx.x * TX;
    const int oy = blockIdx.y * TY;
    const long base = (long)blockIdx.z * (HH * WW);

    u64 kv[5];
    kv[0] = pk2(K0f, K0f); kv[1] = pk2(K1f, K1f); kv[2] = pk2(K2f, K2f);
    kv[3] = pk2(K3f, K3f); kv[4] = pk2(K4f, K4f);
    const u64 neg1 = pk2(-1.f, -1.f);
    const bool interior = (ox != 0) && (ox != WW - TX) && (oy != 0) && (oy != HH - TY);

    // ---------- S0: coalesced load of x tile [48 x 144], row-major ----------
    #pragma unroll 1
    for (int i = tid; i < 48 * 36; i += 256) {
        int r = i / 36, c4 = i - 36 * r;
        int gy = oy - 8 + r, gx = ox - 8 + 4 * c4;   // gx multiple of 4
        float4 v = make_float4(0.f, 0.f, 0.f, 0.f);
        if ((unsigned)gy < (unsigned)HH && (unsigned)gx < (unsigned)WW)
            v = *(const float4*)(x + base + (long)gy * WW + gx);
        *(float4*)(smX + r * PX + 4 * c4) = v;
    }
    __syncthreads();

    // ---------- S1: scalar h-conv of x -> stT [48 x 136] ----------
    #pragma unroll 1
    for (int i = tid; i < 432; i += 256) {
        int r = i % 48, s = i / 48;
        const float* sp = smX + r * PX + 16 * s;
        float* dp = smT + r * PT + 16 * s;
        float a[24];
        #pragma unroll
        for (int q = 0; q < 4; q++) {
            float4 v = ((const float4*)sp)[q];
            a[4*q] = v.x; a[4*q+1] = v.y; a[4*q+2] = v.z; a[4*q+3] = v.w;
        }
        float o[16];
        #pragma unroll
        for (int k = 0; k < 8; k++) o[k] = conv9s(a + k);
        if (s < 8) {
            #pragma unroll
            for (int q = 4; q < 6; q++) {
                float4 v = ((const float4*)sp)[q];
                a[4*q] = v.x; a[4*q+1] = v.y; a[4*q+2] = v.z; a[4*q+3] = v.w;
            }
            #pragma unroll
            for (int k = 8; k < 16; k++) o[k] = conv9s(a + k);
            #pragma unroll
            for (int q = 0; q < 4; q++)
                ((float4*)dp)[q] = make_float4(o[4*q], o[4*q+1], o[4*q+2], o[4*q+3]);
        } else {
            ((float4*)dp)[0] = make_float4(o[0], o[1], o[2], o[3]);
            ((float4*)dp)[1] = make_float4(o[4], o[5], o[6], o[7]);
        }
    }
    __syncthreads();

    // ---------- S2: v-conv (2-col u64 items) -> mean; d = (x-mean)*mask -> sd ----------
    // item (cp, ck): t cols (2cp, 2cp+1) [img gx0 = ox-4+2cp], d rows 8ck..8ck+7
    #pragma unroll 1
    for (int i = tid; i < 340; i += 256) {
        int cp = i % 68, ck = i / 68;
        const int y0 = 8 * ck;
        const float* tp = smT + y0 * PT + 2 * cp;
        u64 a[16];
        #pragma unroll
        for (int q = 0; q < 16; q++) a[q] = *(const u64*)(tp + q * PT);

        const int gx0 = ox - 4 + 2 * cp;
        const float* xp = x + base + (long)(oy - 4 + y0) * WW + gx0;
        float* dp = smX + y0 * PD + 2 * cp;

        if (interior) {
            #pragma unroll
            for (int k = 0; k < 8; k++) {
                u64 mp = conv9p(a + k, kv);
                u64 xv = *(const u64*)(xp + (long)k * WW);
                *(u64*)(dp + k * PD) = f2fma(mp, neg1, xv);
            }
        } else {
            const bool cE = (unsigned)gx0 < (unsigned)WW;
            const bool cO = (unsigned)(gx0 + 1) < (unsigned)WW;
            #pragma unroll
            for (int k = 0; k < 8; k++) {
                u64 mp = conv9p(a + k, kv);
                int gy = oy - 4 + y0 + k;
                bool rok = (unsigned)gy < (unsigned)HH;
                float e = (rok && cE) ? xp[(long)k * WW] : 0.f;
                float o = (rok && cO) ? xp[(long)k * WW + 1] : 0.f;
                u64 msk = pk2((rok && cE) ? 1.f : 0.f, (rok && cO) ? 1.f : 0.f);
                *(u64*)(dp + k * PD) = f2mul(f2fma(mp, neg1, pk2(e, o)), msk);
            }
        }
    }
    __syncthreads();

    // ---------- S3: scalar h-conv of d^2 -> st2 [40 x 128] ----------
    #pragma unroll 1
    for (int i = tid; i < 320; i += 256) {
        int y = i % 40, s = i / 40;
        const float* dpp = smX + y * PD + 16 * s;
        float a[24];
        #pragma unroll
        for (int q = 0; q < 6; q++) {
            float4 v = ((const float4*)dpp)[q];
            a[4*q]   = v.x * v.x;
            a[4*q+1] = v.y * v.y;
            a[4*q+2] = v.z * v.z;
            a[4*q+3] = v.w * v.w;
        }
        float* tp2 = smT + y * P2 + 16 * s;
        #pragma unroll
        for (int q = 0; q < 4; q++) {
            float4 o;
            o.x = conv9s(a + 4*q);
            o.y = conv9s(a + 4*q + 1);
            o.z = conv9s(a + 4*q + 2);
            o.w = conv9s(a + 4*q + 3);
            ((float4*)tp2)[q] = o;
        }
    }
    __syncthreads();

    // ---------- S4: v-conv (2-col u64 items) -> var; finalize; STG.64 ----------
    // item: out cols (ox+2cu, +1), out rows 8ck..8ck+7.  Exactly 256 items.
    {
        int cu = tid & 63, ck = tid >> 6;
        const int y0 = 8 * ck;
        const float* tp = smT + y0 * P2 + 2 * cu;
        u64 a[16];
        #pragma unroll
        for (int q = 0; q < 16; q++) a[q] = *(const u64*)(tp + q * P2);

        const float* dpp = smX + (y0 + 4) * PD + 2 * cu + 4;
        float* op = out + base + (long)(oy + y0) * WW + ox + 2 * cu;
        #pragma unroll
        for (int k = 0; k < 8; k++) {
            V2 v; v.u = conv9p(a + k, kv);
            V2 d; d.u = *(const u64*)(dpp + k * PD);
            float m0 = (v.s[0] > 0.25f) ? rsqrtf(v.s[0]) : 1.f;
            float m1 = (v.s[1] > 0.25f) ? rsqrtf(v.s[1]) : 1.f;
            *(float2*)(op + (long)k * WW) = make_float2(d.s[0] * m0, d.s[1] * m1);
        }
    }
}

extern "C" void kernel_launch(void* const* d_in, const int* in_sizes, int n_in,
                              void* d_out, int out_size) {
    const float* x = (const float*)d_in[0];
    float* out = (float*)d_out;
    int B = in_sizes[0] / (HH * WW);
    cudaFuncSetAttribute(lcn_kernel, cudaFuncAttributeMaxDynamicSharedMemorySize, SMEM_BYTES);
    dim3 grid(WW / TX, HH / TY, B);
    lcn_kernel<<<grid, 256, SMEM_BYTES>>>(x, out);
}

// round 10
// speedup vs baseline: 1.4241x; 1.0329x over previous
#include <cuda_runtime.h>

// Local contrast normalization, fused, row-major dataflow with streaming v-convs.
//  S0: coalesced LDG x tile -> smem
//  S1: scalar h-conv (FFMA-imm), 24-col segments -> stT
//  S2: v-conv via 9-deep packed accumulators, 10-row chunks; d=(x(LDG)-mean)*mask -> sd
//  S3: scalar h-conv of d^2, 24-col segments -> st2
//  S4: v-conv via packed accumulators, 8-row chunks; out = d * (var>0.25 ? rsqrt : 1)
// Taps u[i]=exp(-(i-4.5)^2/3)/S (asymmetric center: K0 only at j=0), SAME zero-pad.
// Vertical tap weight for offset j: w(j) = j<=4 ? j : 9-j   (K-index into K0..K4)

typedef unsigned long long u64;

static constexpr int HH = 512, WW = 512;
static constexpr int TX = 128, TY = 32;

static constexpr int PX = 148;   // sx : 48 x 144 used (592B = 37*16 odd)
static constexpr int PT = 140;   // stT: 48 x 136 used (560B = 35*16 odd)
static constexpr int PD = 140;   // sd : 40 x 136 used (aliases sx region)
static constexpr int P2 = 132;   // st2: 40 x 128 used (528B = 33*16 odd, aliases stT)

static constexpr int OFF_X = 48 * PT;                            // 6720 floats
static constexpr int SMEM_BYTES = (OFF_X + 48 * PX + 8) * 4;     // 55328 B

#define K0f 0.000381553f
#define K1f 0.00549127f
#define K2f 0.04057532f
#define K3f 0.15392929f
#define K4f 0.29981330f

union V2 { u64 u; float s[2]; };

__device__ __forceinline__ u64 pk2(float a, float b) {
    V2 t; t.s[0] = a; t.s[1] = b; return t.u;
}
__device__ __forceinline__ u64 f2mul(u64 a, u64 b) {
    u64 d; asm("mul.rn.f32x2 %0, %1, %2;" : "=l"(d) : "l"(a), "l"(b)); return d;
}
__device__ __forceinline__ u64 f2fma(u64 a, u64 b, u64 c) {
    u64 d; asm("fma.rn.f32x2 %0, %1, %2, %3;" : "=l"(d) : "l"(a), "l"(b), "l"(c)); return d;
}

// scalar 9-tap conv, literal taps -> FFMA-imm (rt 1)
__device__ __forceinline__ float conv9s(const float* a) {
    float acc = K0f * a[0];
    acc = fmaf(K1f, a[1], acc);
    acc = fmaf(K2f, a[2], acc);
    acc = fmaf(K3f, a[3], acc);
    acc = fmaf(K4f, a[4], acc);
    acc = fmaf(K4f, a[5], acc);
    acc = fmaf(K3f, a[6], acc);
    acc = fmaf(K2f, a[7], acc);
    acc = fmaf(K1f, a[8], acc);
    return acc;
}

__global__ __launch_bounds__(256, 4)
void lcn_kernel(const float* __restrict__ x, float* __restrict__ out) {
    extern __shared__ float sm[];
    float* smT = sm;            // stT, later st2
    float* smX = sm + OFF_X;    // sx, later sd

    const int tid = threadIdx.x;
    const int ox = blockIdx.x * TX;
    const int oy = blockIdx.y * TY;
    const long base = (long)blockIdx.z * (HH * WW);

    u64 kv[5];
    kv[0] = pk2(K0f, K0f); kv[1] = pk2(K1f, K1f); kv[2] = pk2(K2f, K2f);
    kv[3] = pk2(K3f, K3f); kv[4] = pk2(K4f, K4f);
    const u64 neg1 = pk2(-1.f, -1.f);
    const bool interior = (ox != 0) && (ox != WW - TX) && (oy != 0) && (oy != HH - TY);

    // ---------- S0: coalesced load of x tile [48 x 144] ----------
    if (interior) {
        const float* xb = x + base + (long)(oy - 8) * WW + (ox - 8);
        #pragma unroll 1
        for (int i = tid; i < 1536; i += 256) {             // main: 32 f4/row
            int r = i >> 5, c4 = i & 31;
            *(float4*)(smX + r * PX + 4 * c4) = *(const float4*)(xb + (long)r * WW + 4 * c4);
        }
        #pragma unroll 1
        for (int i = tid; i < 192; i += 256) {              // halo: 4 f4/row
            int r = i >> 2, c4 = 32 + (i & 3);
            *(float4*)(smX + r * PX + 4 * c4) = *(const float4*)(xb + (long)r * WW + 4 * c4);
        }
    } else {
        #pragma unroll 1
        for (int i = tid; i < 48 * 36; i += 256) {
            int r = i / 36, c4 = i - 36 * r;
            int gy = oy - 8 + r, gx = ox - 8 + 4 * c4;
            float4 v = make_float4(0.f, 0.f, 0.f, 0.f);
            if ((unsigned)gy < (unsigned)HH && (unsigned)gx < (unsigned)WW)
                v = *(const float4*)(x + base + (long)gy * WW + gx);
            *(float4*)(smX + r * PX + 4 * c4) = v;
        }
    }
    __syncthreads();

    // ---------- S1: scalar h-conv of x -> stT, 24-col segments (288 items) ----------
    #pragma unroll 1
    for (int i = tid; i < 288; i += 256) {
        int r = i % 48, s = i / 48;           // s = 0..5; c0 = 24s; seg 5 stores 16 cols
        const int c0 = 24 * s;
        const float* sp = smX + r * PX + c0;
        float a[32];
        #pragma unroll
        for (int q = 0; q < 8; q++) {          // unified 8-f4 window (overread safe, padded)
            float4 v = ((const float4*)sp)[q];
            a[4*q] = v.x; a[4*q+1] = v.y; a[4*q+2] = v.z; a[4*q+3] = v.w;
        }
        float* dp = smT + r * PT + c0;
        #pragma unroll
        for (int m = 0; m < 4; m++) {
            float4 o;
            o.x = conv9s(a + 4*m);     o.y = conv9s(a + 4*m + 1);
            o.z = conv9s(a + 4*m + 2); o.w = conv9s(a + 4*m + 3);
            ((float4*)dp)[m] = o;
        }
        if (s < 5) {
            #pragma unroll
            for (int m = 4; m < 6; m++) {
                float4 o;
                o.x = conv9s(a + 4*m);     o.y = conv9s(a + 4*m + 1);
                o.z = conv9s(a + 4*m + 2); o.w = conv9s(a + 4*m + 3);
                ((float4*)dp)[m] = o;
            }
        }
    }
    __syncthreads();

    // ---------- S2: streaming v-conv -> mean; d=(x-mean)*mask -> sd (272 items) ----------
    // item (cp, ch): t cols (2cp, 2cp+1), d rows 10ch..10ch+9
    #pragma unroll 1
    for (int i = tid; i < 272; i += 256) {
        int cp = i % 68, ch = i / 68;
        const int y0 = 10 * ch;
        const int gx0 = ox - 4 + 2 * cp;                 // always even
        const float* xp = x + base + (long)(oy - 4 + y0) * WW + gx0;
        const float* tp = smT + y0 * PT + 2 * cp;
        float* dp = smX + y0 * PD + 2 * cp;

        // prefetch x rows (masked on border)
        u64 xr[10];
        float msk[10];
        if (interior) {
            #pragma unroll
            for (int k = 0; k < 10; k++) { xr[k] = *(const u64*)(xp + (long)k * WW); msk[k] = 1.f; }
        } else {
            const bool cok = (unsigned)gx0 < (unsigned)WW;
            #pragma unroll
            for (int k = 0; k < 10; k++) {
                int gy = oy - 4 + y0 + k;
                bool ok = cok && ((unsigned)gy < (unsigned)HH);
                xr[k] = ok ? *(const u64*)(xp + (long)k * WW) : 0ULL;
                msk[k] = ok ? 1.f : 0.f;
            }
        }

        u64 acc[9];
        #pragma unroll
        for (int q = 0; q < 18; q++) {
            u64 tv = *(const u64*)(tp + q * PT);
            #pragma unroll
            for (int y = (q > 8 ? q - 8 : 0); y <= (q < 9 ? q : 9); y++) {
                int j = q - y;                         // tap offset 0..8
                int w = (j <= 4) ? j : (9 - j);        // K-index (asymmetric taps!)
                if (j == 0) acc[y % 9] = f2mul(kv[w], tv);
                else        acc[y % 9] = f2fma(kv[w], tv, acc[y % 9]);
            }
            if (q >= 8) {
                int y = q - 8;
                u64 d = f2fma(acc[y % 9], neg1, xr[y]);          // x - mean
                d = f2mul(d, pk2(msk[y], msk[y]));
                *(u64*)(dp + y * PD) = d;
            }
        }
    }
    __syncthreads();

    // ---------- S3: scalar h-conv of d^2 -> st2, 24-col segments (240 items) ----------
    #pragma unroll 1
    for (int i = tid; i < 240; i += 256) {
        int y = i % 40, s = i / 40;          // s = 0..5; seg 5 stores 8 cols
        const int c0 = 24 * s;
        const float* dpp = smX + y * PD + c0;
        float a[32];
        #pragma unroll
        for (int q = 0; q < 8; q++) {
            float4 v = ((const float4*)dpp)[q];
            a[4*q]   = v.x * v.x;
            a[4*q+1] = v.y * v.y;
            a[4*q+2] = v.z * v.z;
            a[4*q+3] = v.w * v.w;
        }
        float* tp2 = smT + y * P2 + c0;
        #pragma unroll
        for (int m = 0; m < 2; m++) {
            float4 o;
            o.x = conv9s(a + 4*m);     o.y = conv9s(a + 4*m + 1);
            o.z = conv9s(a + 4*m + 2); o.w = conv9s(a + 4*m + 3);
            ((float4*)tp2)[m] = o;
        }
        if (s < 5) {
            #pragma unroll
            for (int m = 2; m < 6; m++) {
                float4 o;
                o.x = conv9s(a + 4*m);     o.y = conv9s(a + 4*m + 1);
                o.z = conv9s(a + 4*m + 2); o.w = conv9s(a + 4*m + 3);
                ((float4*)tp2)[m] = o;
            }
        }
    }
    __syncthreads();

    // ---------- S4: streaming v-conv -> var; finalize; STG.64 (256 items) ----------
    {
        int cu = tid & 63, ck = tid >> 6;
        const int y0 = 8 * ck;
        const float* tp = smT + y0 * P2 + 2 * cu;
        const float* sdb = smX + (y0 + 4) * PD + 2 * cu + 4;
        float* op = out + base + (long)(oy + y0) * WW + ox + 2 * cu;

        u64 dr[8];
        #pragma unroll
        for (int k = 0; k < 8; k++) dr[k] = *(const u64*)(sdb + k * PD);

        u64 acc[8];
        #pragma unroll
        for (int q = 0; q < 16; q++) {
            u64 tv = *(const u64*)(tp + q * P2);
            #pragma unroll
            for (int y = (q > 8 ? q - 8 : 0); y <= (q < 8 ? q : 7); y++) {
                int j = q - y;                         // tap offset 0..8
                int w = (j <= 4) ? j : (9 - j);        // K-index (asymmetric taps!)
                if (j == 0) acc[y] = f2mul(kv[w], tv);
                else        acc[y] = f2fma(kv[w], tv, acc[y]);
            }
            if (q >= 8) {
                int y = q - 8;
                V2 v; v.u = acc[y];
                V2 d; d.u = dr[y];
                float m0 = (v.s[0] > 0.25f) ? rsqrtf(v.s[0]) : 1.f;
                float m1 = (v.s[1] > 0.25f) ? rsqrtf(v.s[1]) : 1.f;
                *(float2*)(op + (long)y * WW) = make_float2(d.s[0] * m0, d.s[1] * m1);
            }
        }
    }
}

extern "C" void kernel_launch(void* const* d_in, const int* in_sizes, int n_in,
                              void* d_out, int out_size) {
    const float* x = (const float*)d_in[0];
    float* out = (float*)d_out;
    int B = in_sizes[0] / (HH * WW);
    cudaFuncSetAttribute(lcn_kernel, cudaFuncAttributeMaxDynamicSharedMemorySize, SMEM_BYTES);
    dim3 grid(WW / TX, HH / TY, B);
    lcn_kernel<<<grid, 256, SMEM_BYTES>>>(x, out);
}